// round 14
// baseline (speedup 1.0000x reference)
#include <cuda_runtime.h>
#include <cuda_fp16.h>
#include <cstdint>

#define EPS 0.001f
#define NF   64
#define CCH  256
#define NPIX 1600        // 40*40
#define RTOT 4096        // N*K = 512*8
#define HID  512
#define DD   512
#define K1   12544       // 49*256
#define NCHUNK 392       // K1/32
#define TILE_BYTES 8192  // 128 rows x 32 k (fp16), fragment order
#define TILE_HALVES 4096

// ---- scratch (static __device__ per allocation rules) ----
__device__ __half g_imgH[(size_t)NF * NPIX * CCH];            // NHWC fp16 images (52 MB)
__device__ __half g_w1tT[(size_t)4 * NCHUNK * TILE_HALVES];   // B1 frag tiles (paired-nsub layout)
__device__ __half g_roiT[(size_t)32 * NCHUNK * TILE_HALVES];  // A1 frag tiles (103 MB)
__device__ __half g_h1T [(size_t)32 * 16 * TILE_HALVES];      // h1 as A2 frag tiles
__device__ __half g_w2T [(size_t)4 * 16 * TILE_HALVES];       // B2 frag tiles (paired-nsub layout)

// ---------------- image transpose NCHW f32 -> NHWC f16 ----------------
__global__ void transpose_img(const float* __restrict__ in)
{
    __shared__ float s[64][33];
    const int f  = blockIdx.z;
    const float* src = in + (size_t)f * CCH * NPIX;
    const int p0 = blockIdx.x * 32;
    const int c0 = blockIdx.y * 64;
    #pragma unroll
    for (int i = threadIdx.y; i < 64; i += 8)
        s[i][threadIdx.x] = src[(size_t)(c0 + i) * NPIX + p0 + threadIdx.x];
    __syncthreads();
    __half2* dst = (__half2*)g_imgH + (size_t)f * NPIX * 128 + (c0 >> 1) + threadIdx.x;
    #pragma unroll
    for (int i = threadIdx.y; i < 32; i += 8)
        dst[(size_t)(p0 + i) * 128] =
            __floats2half2_rn(s[2 * threadIdx.x][i], s[2 * threadIdx.x + 1][i]);
}

// ---------------- w1 -> fp16 B-fragment tiles (paired-nsub 16B slots) ----------------
__global__ void __launch_bounds__(128) transpose_w1(const float* __restrict__ w1)
{
    __shared__ __half s[K1];
    const int o = blockIdx.x;
    const int ntile = o >> 7, col = o & 127;
    const int nsub = col >> 3, np = nsub >> 1, hf = nsub & 1, gcol = col & 7;
    const float* src = w1 + (size_t)o * K1;
    for (int i = threadIdx.x; i < K1; i += 128)
        s[i] = __float2half(src[i]);
    __syncthreads();
    char* base = (char*)g_w1tT + (size_t)ntile * NCHUNK * TILE_BYTES;
    for (int k2 = threadIdx.x; k2 < K1 / 2; k2 += 128) {
        const int k = k2 * 2;
        const int hw = k >> 8, c = k & 255;
        const __half2 v = __halves2half2(s[c * 49 + hw], s[(c + 1) * 49 + hw]);
        const int chunk = k >> 5, kk = k & 31;
        const int ks = kk >> 4, kkk = kk & 15;
        const int tg = (kkk & 7) >> 1;
        const int b_idx = (kkk >= 8) ? 1 : 0;
        const uint32_t off = np * 1024 + ks * 512 + (gcol * 4 + tg) * 16 + hf * 8 + b_idx * 4;
        *(__half2*)(base + (size_t)chunk * TILE_BYTES + off) = v;
    }
}

// ---------------- w2 -> fp16 B-fragment tiles (paired-nsub) ----------------
__global__ void repack_w2(const float* __restrict__ w2)
{
    const int o = blockIdx.x;
    const int ntile = o >> 7, col = o & 127;
    const int nsub = col >> 3, np = nsub >> 1, hf = nsub & 1, gcol = col & 7;
    for (int k2 = threadIdx.x; k2 < DD / 2; k2 += blockDim.x) {
        const int k = k2 * 2;
        const float v0 = __ldg(&w2[(size_t)o * DD + k]);
        const float v1 = __ldg(&w2[(size_t)o * DD + k + 1]);
        const int chunk = k >> 5, kk = k & 31;
        const int ks = kk >> 4, kkk = kk & 15;
        const int tg = (kkk & 7) >> 1;
        const int b_idx = (kkk >= 8) ? 1 : 0;
        const uint32_t off = np * 1024 + ks * 512 + (gcol * 4 + tg) * 16 + hf * 8 + b_idx * 4;
        *(__half2*)((char*)g_w2T + (size_t)(ntile * 16 + chunk) * TILE_BYTES + off) =
            __floats2half2_rn(v0, v1);
    }
}

// ---------------- fused RoIAlign gather -> fp16 A fragment tiles ----------------
// (unchanged — proven at ~45us)
union U4 { uint4 u; __half2 h[4]; };

__global__ void __launch_bounds__(256) roi_gather_frag(const int* __restrict__ kf,
                                                       const float* __restrict__ boxes)
{
    __shared__ uint32_t s[16 * 132];
    const int blk = blockIdx.x;
    const int h   = blockIdx.y;
    const int mtile = blk >> 3, sub = blk & 7;
    const int tid = threadIdx.x, lane = tid & 31, wp = tid >> 5;
    const int rA = blk * 16 + wp, rB = rA + 8;

    const int fA = kf[rA], fB = kf[rB];
    const float ax1 = boxes[rA * 4 + 0] * 40.f, ay1 = boxes[rA * 4 + 1] * 40.f;
    const float ax2 = boxes[rA * 4 + 2] * 40.f, ay2 = boxes[rA * 4 + 3] * 40.f;
    const float bx1 = boxes[rB * 4 + 0] * 40.f, by1 = boxes[rB * 4 + 1] * 40.f;
    const float bx2 = boxes[rB * 4 + 2] * 40.f, by2 = boxes[rB * 4 + 3] * 40.f;
    const float abw = (ax2 - ax1) * (1.f / 7.f), abh = (ay2 - ay1) * (1.f / 7.f);
    const float bbw = (bx2 - bx1) * (1.f / 7.f), bbh = (by2 - by1) * (1.f / 7.f);

    const uint4* imgA = (const uint4*)(g_imgH + (size_t)fA * NPIX * CCH);
    const uint4* imgB = (const uint4*)(g_imgH + (size_t)fB * NPIX * CCH);
    char* outb = (char*)g_roiT + (size_t)mtile * NCHUNK * TILE_BYTES + sub * 1024;

    const float YA = ay1 + (h + 0.5f) * abh;
    const float ycA = fminf(fmaxf(YA, 0.f), 39.f);
    const int   y0A = (int)ycA, y1iA = min(y0A + 1, 39);
    const float lyA = ycA - (float)y0A;
    const bool  vyA = (YA > -1.f) && (YA < 40.f);

    const float YB = by1 + (h + 0.5f) * bbh;
    const float ycB = fminf(fmaxf(YB, 0.f), 39.f);
    const int   y0B = (int)ycB, y1iB = min(y0B + 1, 39);
    const float lyB = ycB - (float)y0B;
    const bool  vyB = (YB > -1.f) && (YB < 40.f);

    const uint32_t wSw = ((uint32_t)(lane * 4)) ^ ((((uint32_t)lane >> 3) & 1u) << 2);
    uint32_t* wrA = s + wp * 132 + wSw;
    uint32_t* wrB = s + (wp + 8) * 132 + wSw;

    const int cc0 = lane >> 3,        ks0 = (lane >> 2) & 1, tg0 = lane & 3;
    const int cc1 = (lane + 32) >> 3, ks1 = ks0,             tg1 = tg0;
    const int tA0 = cc0 * 16 + ks0 * 8 + tg0;
    const int tA1 = cc1 * 16 + ks1 * 8 + tg1;
    const int pA0 = tA0 ^ (((tA0 >> 5) & 1) << 2);
    const int pA4 = (tA0 + 4) ^ (((tA0 >> 5) & 1) << 2);
    const int pB0 = tA1 ^ (((tA1 >> 5) & 1) << 2);
    const int pB4 = (tA1 + 4) ^ (((tA1 >> 5) & 1) << 2);

    for (int w = 0; w < 7; ++w) {
        const float XA = ax1 + (w + 0.5f) * abw;
        const float xcA = fminf(fmaxf(XA, 0.f), 39.f);
        const int   x0A = (int)xcA, x1iA = min(x0A + 1, 39);
        const float lxA = xcA - (float)x0A;
        float a00 = (1.f - lyA) * (1.f - lxA), a01 = (1.f - lyA) * lxA;
        float a10 = lyA * (1.f - lxA),         a11 = lyA * lxA;
        if (!(vyA && XA > -1.f && XA < 40.f)) { a00 = a01 = a10 = a11 = 0.f; }
        const float XB = bx1 + (w + 0.5f) * bbw;
        const float xcB = fminf(fmaxf(XB, 0.f), 39.f);
        const int   x0B = (int)xcB, x1iB = min(x0B + 1, 39);
        const float lxB = xcB - (float)x0B;
        float b00 = (1.f - lyB) * (1.f - lxB), b01 = (1.f - lyB) * lxB;
        float b10 = lyB * (1.f - lxB),         b11 = lyB * lxB;
        if (!(vyB && XB > -1.f && XB < 40.f)) { b00 = b01 = b10 = b11 = 0.f; }

        U4 cA00, cA01, cA10, cA11, cB00, cB01, cB10, cB11;
        cA00.u = imgA[(y0A  * 40 + x0A ) * 32 + lane];
        cA01.u = imgA[(y0A  * 40 + x1iA) * 32 + lane];
        cA10.u = imgA[(y1iA * 40 + x0A ) * 32 + lane];
        cA11.u = imgA[(y1iA * 40 + x1iA) * 32 + lane];
        cB00.u = imgB[(y0B  * 40 + x0B ) * 32 + lane];
        cB01.u = imgB[(y0B  * 40 + x1iB) * 32 + lane];
        cB10.u = imgB[(y1iB * 40 + x0B ) * 32 + lane];
        cB11.u = imgB[(y1iB * 40 + x1iB) * 32 + lane];

        U4 oA, oB;
        #pragma unroll
        for (int j = 0; j < 4; ++j) {
            float2 f0 = __half22float2(cA00.h[j]);
            float2 f1 = __half22float2(cA01.h[j]);
            float2 f2 = __half22float2(cA10.h[j]);
            float2 f3 = __half22float2(cA11.h[j]);
            oA.h[j] = __floats2half2_rn(
                f0.x * a00 + f1.x * a01 + f2.x * a10 + f3.x * a11,
                f0.y * a00 + f1.y * a01 + f2.y * a10 + f3.y * a11);
            f0 = __half22float2(cB00.h[j]);
            f1 = __half22float2(cB01.h[j]);
            f2 = __half22float2(cB10.h[j]);
            f3 = __half22float2(cB11.h[j]);
            oB.h[j] = __floats2half2_rn(
                f0.x * b00 + f1.x * b01 + f2.x * b10 + f3.x * b11,
                f0.y * b00 + f1.y * b01 + f2.y * b10 + f3.y * b11);
        }
        *(uint4*)wrA = oA.u;
        *(uint4*)wrB = oB.u;
        __syncwarp();

        const int hw = h * 7 + w;
        {
            uint4 wv;
            wv.x = s[wp * 132 + pA0];
            wv.y = s[(wp + 8) * 132 + pA0];
            wv.z = s[wp * 132 + pA4];
            wv.w = s[(wp + 8) * 132 + pA4];
            *(uint4*)(outb + (size_t)(hw * 8 + cc0) * TILE_BYTES
                      + (ks0 * 32 + wp * 4 + tg0) * 16) = wv;
            wv.x = s[wp * 132 + pB0];
            wv.y = s[(wp + 8) * 132 + pB0];
            wv.z = s[wp * 132 + pB4];
            wv.w = s[(wp + 8) * 132 + pB4];
            *(uint4*)(outb + (size_t)(hw * 8 + cc1) * TILE_BYTES
                      + (ks1 * 32 + wp * 4 + tg1) * 16) = wv;
        }
        __syncwarp();
    }
}

// == fp16 MMA GEMM: 128x128x32 CTA, 8 warps ks-split, 6-stage ring,
//    1 chunk/barrier + register double-buffered fragments ==
#define NSTAGE 6
#define STAGE_BYTES 16384
#define SM_TOTAL (NSTAGE * STAGE_BYTES)   // 96 KB

__device__ __forceinline__ void cp16(void* smem_dst, const void* gmem_src) {
    unsigned s = (unsigned)__cvta_generic_to_shared(smem_dst);
    asm volatile("cp.async.cg.shared.global [%0], [%1], 16;" :: "r"(s), "l"(gmem_src));
}
__device__ __forceinline__ void cp_commit() { asm volatile("cp.async.commit_group;"); }
template<int N> __device__ __forceinline__ void cp_wait() {
    asm volatile("cp.async.wait_group %0;" :: "n"(N));
}

__global__ void __launch_bounds__(256, 1)
gemm_tc(const char* __restrict__ Afrag, const char* __restrict__ Bfrag, int nchunk,
        char* __restrict__ outFrag, float* __restrict__ outMax,
        const float* __restrict__ bias, const float* __restrict__ gamma,
        const float* __restrict__ beta, const float* __restrict__ mean,
        const float* __restrict__ var)
{
    extern __shared__ char sm[];
    const int tid = threadIdx.x, lane = tid & 31, wid = tid >> 5;
    const int ksw = wid >> 2;                 // k16-slice this warp owns
    const int wq  = wid & 3;                  // quad
    const int warp_m = wq >> 1, warp_n = wq & 1;
    const int ntile = blockIdx.x, mtile = blockIdx.y;

    const char* Ag = Afrag + (size_t)mtile * nchunk * TILE_BYTES;
    const char* Bg = Bfrag + (size_t)ntile * nchunk * TILE_BYTES;

    float acc[4][8][4];
    #pragma unroll
    for (int mt = 0; mt < 4; ++mt)
        #pragma unroll
        for (int nt = 0; nt < 8; ++nt)
            #pragma unroll
            for (int j = 0; j < 4; ++j) acc[mt][nt][j] = 0.f;

    // prologue: stages 0..4, one commit group each
    #pragma unroll
    for (int t = 0; t < 5; ++t) {
        char* sa = sm + t * STAGE_BYTES;
        #pragma unroll
        for (int i = 0; i < 2; ++i) {
            const int off = (tid + i * 256) * 16;
            cp16(sa + off,        Ag + (size_t)t * TILE_BYTES + off);
            cp16(sa + 8192 + off, Bg + (size_t)t * TILE_BYTES + off);
        }
        cp_commit();
    }

    const int aBase = warp_m * 4096 + ksw * 512 + lane * 16;
    const int bBase = 8192 + warp_n * 4096 + ksw * 512 + lane * 16;

    // pre-load fragments for chunk 0 (stage 0 guaranteed after wait<4>)
    cp_wait<4>();
    __syncthreads();
    uint4 fa[4], fb[4];
    #pragma unroll
    for (int mt = 0; mt < 4; ++mt) fa[mt] = *(const uint4*)(sm + aBase + mt * 1024);
    #pragma unroll
    for (int np = 0; np < 4; ++np) fb[np] = *(const uint4*)(sm + bBase + np * 1024);

    int stL = 5;                               // next ring slot to fill
    for (int t = 0; t < nchunk; ++t) {
        cp_wait<3>();                          // stages t and t+1 guaranteed landed
        __syncthreads();

        const int tl = t + 5;
        if (tl < nchunk) {
            char* sa = sm + stL * STAGE_BYTES;
            #pragma unroll
            for (int i = 0; i < 2; ++i) {
                const int off = (tid + i * 256) * 16;
                cp16(sa + off,        Ag + (size_t)tl * TILE_BYTES + off);
                cp16(sa + 8192 + off, Bg + (size_t)tl * TILE_BYTES + off);
            }
        }
        cp_commit();
        if (++stL == NSTAGE) stL = 0;

        // prefetch fragments for chunk t+1 (overlaps with this chunk's HMMAs)
        uint4 na[4], nb[4];
        if (t + 1 < nchunk) {
            const char* Sn = sm + ((t + 1) % NSTAGE) * STAGE_BYTES;
            #pragma unroll
            for (int mt = 0; mt < 4; ++mt) na[mt] = *(const uint4*)(Sn + aBase + mt * 1024);
            #pragma unroll
            for (int np = 0; np < 4; ++np) nb[np] = *(const uint4*)(Sn + bBase + np * 1024);
        }

        #pragma unroll
        for (int np = 0; np < 4; ++np) {
            #pragma unroll
            for (int mt = 0; mt < 4; ++mt) {
                asm volatile(
                    "mma.sync.aligned.m16n8k16.row.col.f32.f16.f16.f32 "
                    "{%0,%1,%2,%3}, {%4,%5,%6,%7}, {%8,%9}, {%0,%1,%2,%3};"
                    : "+f"(acc[mt][np * 2][0]), "+f"(acc[mt][np * 2][1]),
                      "+f"(acc[mt][np * 2][2]), "+f"(acc[mt][np * 2][3])
                    : "r"(fa[mt].x), "r"(fa[mt].y), "r"(fa[mt].z), "r"(fa[mt].w),
                      "r"(fb[np].x), "r"(fb[np].y));
                asm volatile(
                    "mma.sync.aligned.m16n8k16.row.col.f32.f16.f16.f32 "
                    "{%0,%1,%2,%3}, {%4,%5,%6,%7}, {%8,%9}, {%0,%1,%2,%3};"
                    : "+f"(acc[mt][np * 2 + 1][0]), "+f"(acc[mt][np * 2 + 1][1]),
                      "+f"(acc[mt][np * 2 + 1][2]), "+f"(acc[mt][np * 2 + 1][3])
                    : "r"(fa[mt].x), "r"(fa[mt].y), "r"(fa[mt].z), "r"(fa[mt].w),
                      "r"(fb[np].z), "r"(fb[np].w));
            }
        }

        #pragma unroll
        for (int mt = 0; mt < 4; ++mt) fa[mt] = na[mt];
        #pragma unroll
        for (int np = 0; np < 4; ++np) fb[np] = nb[np];
    }

    const int g = lane >> 2, tg = lane & 3;

    // ---- ks-split combine: warps 4-7 dump partials, warps 0-3 add ----
    __syncthreads();
    {
        float2* red2 = (float2*)sm;   // 128 x 64 float2, XOR-swizzled by (g<<2)
        if (ksw == 1) {
            #pragma unroll
            for (int nt = 0; nt < 8; ++nt) {
                const int col2 = warp_n * 32 + nt * 4 + tg;
                #pragma unroll
                for (int mt = 0; mt < 4; ++mt) {
                    const int row = warp_m * 64 + mt * 16 + g;
                    const int ph = col2 ^ (g << 2);
                    float2 v0; v0.x = acc[mt][nt][0]; v0.y = acc[mt][nt][1];
                    float2 v1; v1.x = acc[mt][nt][2]; v1.y = acc[mt][nt][3];
                    red2[row * 64 + ph] = v0;
                    red2[(row + 8) * 64 + ph] = v1;
                }
            }
        }
        __syncthreads();
        if (ksw == 0) {
            #pragma unroll
            for (int nt = 0; nt < 8; ++nt) {
                const int col2 = warp_n * 32 + nt * 4 + tg;
                #pragma unroll
                for (int mt = 0; mt < 4; ++mt) {
                    const int row = warp_m * 64 + mt * 16 + g;
                    const int ph = col2 ^ (g << 2);
                    const float2 v0 = red2[row * 64 + ph];
                    const float2 v1 = red2[(row + 8) * 64 + ph];
                    acc[mt][nt][0] += v0.x; acc[mt][nt][1] += v0.y;
                    acc[mt][nt][2] += v1.x; acc[mt][nt][3] += v1.y;
                }
            }
        }
        __syncthreads();
    }

    if (outFrag) {
        // stage BN+ReLU tile in smem as half2 (stride 66), then emit A-frag fp16 tiles
        __half2* st2 = (__half2*)sm;
        if (ksw == 0) {
            #pragma unroll
            for (int nt = 0; nt < 8; ++nt) {
                const int c0l = warp_n * 64 + nt * 8 + tg * 2;
                const int cg0 = ntile * 128 + c0l;
                const float s0 = gamma[cg0]     * rsqrtf(var[cg0]     + EPS);
                const float s1 = gamma[cg0 + 1] * rsqrtf(var[cg0 + 1] + EPS);
                const float h0  = (bias[cg0]     - mean[cg0])     * s0 + beta[cg0];
                const float h1v = (bias[cg0 + 1] - mean[cg0 + 1]) * s1 + beta[cg0 + 1];
                #pragma unroll
                for (int mt = 0; mt < 4; ++mt) {
                    const int rowl = warp_m * 64 + mt * 16 + g;
                    st2[rowl * 66 + (c0l >> 1)] = __floats2half2_rn(
                        fmaxf(acc[mt][nt][0] * s0 + h0,  0.f),
                        fmaxf(acc[mt][nt][1] * s1 + h1v, 0.f));
                    st2[(rowl + 8) * 66 + (c0l >> 1)] = __floats2half2_rn(
                        fmaxf(acc[mt][nt][2] * s0 + h0,  0.f),
                        fmaxf(acc[mt][nt][3] * s1 + h1v, 0.f));
                }
            }
        }
        __syncthreads();
        char* dst = outFrag + (size_t)(mtile * 16 + ntile * 4) * TILE_BYTES;
        #pragma unroll
        for (int it = 0; it < 8; ++it) {
            const int u = tid + it * 256;        // 0..2047 (16B slots)
            const int chunkl = u >> 9, sidx = u & 511;
            const int subr = sidx >> 6, rem = sidx & 63;
            const int ks2 = rem >> 5, ln = rem & 31;
            const int g2 = ln >> 2, tg2 = ln & 3;
            const int row = subr * 16 + g2;
            const int kp = chunkl * 16 + ks2 * 8 + tg2;
            uint4 wv;
            wv.x = *(const uint32_t*)&st2[row * 66 + kp];
            wv.y = *(const uint32_t*)&st2[(row + 8) * 66 + kp];
            wv.z = *(const uint32_t*)&st2[row * 66 + kp + 4];
            wv.w = *(const uint32_t*)&st2[(row + 8) * 66 + kp + 4];
            *(uint4*)(dst + (size_t)chunkl * TILE_BYTES + subr * 1024 + rem * 16) = wv;
        }
    } else if (ksw == 0) {
        // fused BN + ReLU + max over 8-row groups -> outMax[node][col]
        const int n0 = ntile * 128 + warp_n * 64;
        #pragma unroll
        for (int nt = 0; nt < 8; ++nt) {
            const int c0 = n0 + nt * 8 + tg * 2;
            const float s0 = gamma[c0]     * rsqrtf(var[c0]     + EPS);
            const float s1 = gamma[c0 + 1] * rsqrtf(var[c0 + 1] + EPS);
            const float h0  = (bias[c0]     - mean[c0])     * s0 + beta[c0];
            const float h1v = (bias[c0 + 1] - mean[c0 + 1]) * s1 + beta[c0 + 1];
            #pragma unroll
            for (int mt = 0; mt < 4; ++mt) {
                float v0 = fmaxf(acc[mt][nt][0] * s0 + h0,  0.f);
                float v1 = fmaxf(acc[mt][nt][1] * s1 + h1v, 0.f);
                float v2 = fmaxf(acc[mt][nt][2] * s0 + h0,  0.f);
                float v3 = fmaxf(acc[mt][nt][3] * s1 + h1v, 0.f);
                #pragma unroll
                for (int d = 4; d <= 16; d <<= 1) {
                    v0 = fmaxf(v0, __shfl_xor_sync(0xffffffffu, v0, d));
                    v1 = fmaxf(v1, __shfl_xor_sync(0xffffffffu, v1, d));
                    v2 = fmaxf(v2, __shfl_xor_sync(0xffffffffu, v2, d));
                    v3 = fmaxf(v3, __shfl_xor_sync(0xffffffffu, v3, d));
                }
                if (lane < 4) {
                    const int node0 = mtile * 16 + warp_m * 8 + mt * 2;
                    float2 a; a.x = v0; a.y = v1;
                    float2 b; b.x = v2; b.y = v3;
                    *(float2*)&outMax[(size_t)node0 * DD + c0] = a;
                    *(float2*)&outMax[(size_t)(node0 + 1) * DD + c0] = b;
                }
            }
        }
    }
}

// ---------------- launch ----------------
extern "C" void kernel_launch(void* const* d_in, const int* in_sizes, int n_in,
                              void* d_out, int out_size)
{
    const float* images = (const float*)d_in[0];
    const int*   kf     = (const int*)  d_in[1];
    const float* boxes  = (const float*)d_in[2];
    const float* w1     = (const float*)d_in[3];
    const float* b1     = (const float*)d_in[4];
    const float* g1     = (const float*)d_in[5];
    const float* bt1    = (const float*)d_in[6];
    const float* m1     = (const float*)d_in[7];
    const float* v1     = (const float*)d_in[8];
    const float* w2     = (const float*)d_in[9];
    const float* b2     = (const float*)d_in[10];
    const float* g2     = (const float*)d_in[11];
    const float* bt2    = (const float*)d_in[12];
    const float* m2     = (const float*)d_in[13];
    const float* v2     = (const float*)d_in[14];
    float* out = (float*)d_out;

    char *roiT, *w1tT, *h1T, *w2T;
    cudaGetSymbolAddress((void**)&roiT, g_roiT);
    cudaGetSymbolAddress((void**)&w1tT, g_w1tT);
    cudaGetSymbolAddress((void**)&h1T,  g_h1T);
    cudaGetSymbolAddress((void**)&w2T,  g_w2T);

    cudaFuncSetAttribute(gemm_tc, cudaFuncAttributeMaxDynamicSharedMemorySize, SM_TOTAL);

    // order chosen so gemm1 is launch #4 (ncu capture slot)
    transpose_img<<<dim3(NPIX / 32, CCH / 64, NF), dim3(32, 8)>>>(images);
    transpose_w1<<<HID, 128>>>(w1);
    roi_gather_frag<<<dim3(256, 7), 256>>>(kf, boxes);
    gemm_tc<<<dim3(4, 32), 256, SM_TOTAL>>>(
        roiT, w1tT, NCHUNK, h1T, nullptr, b1, g1, bt1, m1, v1);
    repack_w2<<<DD, 128>>>(w2);
    gemm_tc<<<dim3(4, 32), 256, SM_TOTAL>>>(
        h1T, w2T, 16, nullptr, out, b2, g2, bt2, m2, v2);
}

// round 16
// speedup vs baseline: 1.1455x; 1.1455x over previous
#include <cuda_runtime.h>
#include <cuda_fp16.h>
#include <cstdint>

#define EPS 0.001f
#define NF   64
#define CCH  256
#define NPIX 1600        // 40*40
#define RTOT 4096        // N*K = 512*8
#define HID  512
#define DD   512
#define K1   12544       // 49*256
#define NCHUNK 392       // K1/32
#define HCHUNK 196       // NCHUNK/2 (per split-K half)
#define TILE_BYTES 8192  // 128 rows x 32 k (fp16), fragment order
#define TILE_HALVES 4096

// ---- scratch (static __device__ per allocation rules) ----
__device__ __half g_imgH[(size_t)NF * NPIX * CCH];            // NHWC fp16 images (52 MB)
__device__ __half g_w1tT[(size_t)4 * NCHUNK * TILE_HALVES];   // B1 frag tiles (paired-nsub layout)
__device__ __half g_roiT[(size_t)32 * NCHUNK * TILE_HALVES];  // A1 frag tiles (103 MB)
__device__ __half g_h1T [(size_t)32 * 16 * TILE_HALVES];      // h1 as A2 frag tiles
__device__ __half g_w2T [(size_t)4 * 16 * TILE_HALVES];       // B2 frag tiles (paired-nsub layout)
__device__ float  g_part[(size_t)2 * RTOT * HID];             // split-K fp32 partials (16 MB)

// ---------------- image transpose NCHW f32 -> NHWC f16 ----------------
__global__ void transpose_img(const float* __restrict__ in)
{
    __shared__ float s[64][33];
    const int f  = blockIdx.z;
    const float* src = in + (size_t)f * CCH * NPIX;
    const int p0 = blockIdx.x * 32;
    const int c0 = blockIdx.y * 64;
    #pragma unroll
    for (int i = threadIdx.y; i < 64; i += 8)
        s[i][threadIdx.x] = src[(size_t)(c0 + i) * NPIX + p0 + threadIdx.x];
    __syncthreads();
    __half2* dst = (__half2*)g_imgH + (size_t)f * NPIX * 128 + (c0 >> 1) + threadIdx.x;
    #pragma unroll
    for (int i = threadIdx.y; i < 32; i += 8)
        dst[(size_t)(p0 + i) * 128] =
            __floats2half2_rn(s[2 * threadIdx.x][i], s[2 * threadIdx.x + 1][i]);
}

// ---------------- w1 -> fp16 B-fragment tiles (paired-nsub 16B slots) ----------------
__global__ void __launch_bounds__(128) transpose_w1(const float* __restrict__ w1)
{
    __shared__ __half s[K1];
    const int o = blockIdx.x;
    const int ntile = o >> 7, col = o & 127;
    const int nsub = col >> 3, np = nsub >> 1, hf = nsub & 1, gcol = col & 7;
    const float* src = w1 + (size_t)o * K1;
    for (int i = threadIdx.x; i < K1; i += 128)
        s[i] = __float2half(src[i]);
    __syncthreads();
    char* base = (char*)g_w1tT + (size_t)ntile * NCHUNK * TILE_BYTES;
    for (int k2 = threadIdx.x; k2 < K1 / 2; k2 += 128) {
        const int k = k2 * 2;
        const int hw = k >> 8, c = k & 255;
        const __half2 v = __halves2half2(s[c * 49 + hw], s[(c + 1) * 49 + hw]);
        const int chunk = k >> 5, kk = k & 31;
        const int ks = kk >> 4, kkk = kk & 15;
        const int tg = (kkk & 7) >> 1;
        const int b_idx = (kkk >= 8) ? 1 : 0;
        const uint32_t off = np * 1024 + ks * 512 + (gcol * 4 + tg) * 16 + hf * 8 + b_idx * 4;
        *(__half2*)(base + (size_t)chunk * TILE_BYTES + off) = v;
    }
}

// ---------------- w2 -> fp16 B-fragment tiles (paired-nsub) ----------------
__global__ void repack_w2(const float* __restrict__ w2)
{
    const int o = blockIdx.x;
    const int ntile = o >> 7, col = o & 127;
    const int nsub = col >> 3, np = nsub >> 1, hf = nsub & 1, gcol = col & 7;
    for (int k2 = threadIdx.x; k2 < DD / 2; k2 += blockDim.x) {
        const int k = k2 * 2;
        const float v0 = __ldg(&w2[(size_t)o * DD + k]);
        const float v1 = __ldg(&w2[(size_t)o * DD + k + 1]);
        const int chunk = k >> 5, kk = k & 31;
        const int ks = kk >> 4, kkk = kk & 15;
        const int tg = (kkk & 7) >> 1;
        const int b_idx = (kkk >= 8) ? 1 : 0;
        const uint32_t off = np * 1024 + ks * 512 + (gcol * 4 + tg) * 16 + hf * 8 + b_idx * 4;
        *(__half2*)((char*)g_w2T + (size_t)(ntile * 16 + chunk) * TILE_BYTES + off) =
            __floats2half2_rn(v0, v1);
    }
}

// ---------------- fused RoIAlign gather -> fp16 A fragment tiles ----------------
// (unchanged — proven at ~45us)
union U4 { uint4 u; __half2 h[4]; };

__global__ void __launch_bounds__(256) roi_gather_frag(const int* __restrict__ kf,
                                                       const float* __restrict__ boxes)
{
    __shared__ uint32_t s[16 * 132];
    const int blk = blockIdx.x;
    const int h   = blockIdx.y;
    const int mtile = blk >> 3, sub = blk & 7;
    const int tid = threadIdx.x, lane = tid & 31, wp = tid >> 5;
    const int rA = blk * 16 + wp, rB = rA + 8;

    const int fA = kf[rA], fB = kf[rB];
    const float ax1 = boxes[rA * 4 + 0] * 40.f, ay1 = boxes[rA * 4 + 1] * 40.f;
    const float ax2 = boxes[rA * 4 + 2] * 40.f, ay2 = boxes[rA * 4 + 3] * 40.f;
    const float bx1 = boxes[rB * 4 + 0] * 40.f, by1 = boxes[rB * 4 + 1] * 40.f;
    const float bx2 = boxes[rB * 4 + 2] * 40.f, by2 = boxes[rB * 4 + 3] * 40.f;
    const float abw = (ax2 - ax1) * (1.f / 7.f), abh = (ay2 - ay1) * (1.f / 7.f);
    const float bbw = (bx2 - bx1) * (1.f / 7.f), bbh = (by2 - by1) * (1.f / 7.f);

    const uint4* imgA = (const uint4*)(g_imgH + (size_t)fA * NPIX * CCH);
    const uint4* imgB = (const uint4*)(g_imgH + (size_t)fB * NPIX * CCH);
    char* outb = (char*)g_roiT + (size_t)mtile * NCHUNK * TILE_BYTES + sub * 1024;

    const float YA = ay1 + (h + 0.5f) * abh;
    const float ycA = fminf(fmaxf(YA, 0.f), 39.f);
    const int   y0A = (int)ycA, y1iA = min(y0A + 1, 39);
    const float lyA = ycA - (float)y0A;
    const bool  vyA = (YA > -1.f) && (YA < 40.f);

    const float YB = by1 + (h + 0.5f) * bbh;
    const float ycB = fminf(fmaxf(YB, 0.f), 39.f);
    const int   y0B = (int)ycB, y1iB = min(y0B + 1, 39);
    const float lyB = ycB - (float)y0B;
    const bool  vyB = (YB > -1.f) && (YB < 40.f);

    const uint32_t wSw = ((uint32_t)(lane * 4)) ^ ((((uint32_t)lane >> 3) & 1u) << 2);
    uint32_t* wrA = s + wp * 132 + wSw;
    uint32_t* wrB = s + (wp + 8) * 132 + wSw;

    const int cc0 = lane >> 3,        ks0 = (lane >> 2) & 1, tg0 = lane & 3;
    const int cc1 = (lane + 32) >> 3, ks1 = ks0,             tg1 = tg0;
    const int tA0 = cc0 * 16 + ks0 * 8 + tg0;
    const int tA1 = cc1 * 16 + ks1 * 8 + tg1;
    const int pA0 = tA0 ^ (((tA0 >> 5) & 1) << 2);
    const int pA4 = (tA0 + 4) ^ (((tA0 >> 5) & 1) << 2);
    const int pB0 = tA1 ^ (((tA1 >> 5) & 1) << 2);
    const int pB4 = (tA1 + 4) ^ (((tA1 >> 5) & 1) << 2);

    for (int w = 0; w < 7; ++w) {
        const float XA = ax1 + (w + 0.5f) * abw;
        const float xcA = fminf(fmaxf(XA, 0.f), 39.f);
        const int   x0A = (int)xcA, x1iA = min(x0A + 1, 39);
        const float lxA = xcA - (float)x0A;
        float a00 = (1.f - lyA) * (1.f - lxA), a01 = (1.f - lyA) * lxA;
        float a10 = lyA * (1.f - lxA),         a11 = lyA * lxA;
        if (!(vyA && XA > -1.f && XA < 40.f)) { a00 = a01 = a10 = a11 = 0.f; }
        const float XB = bx1 + (w + 0.5f) * bbw;
        const float xcB = fminf(fmaxf(XB, 0.f), 39.f);
        const int   x0B = (int)xcB, x1iB = min(x0B + 1, 39);
        const float lxB = xcB - (float)x0B;
        float b00 = (1.f - lyB) * (1.f - lxB), b01 = (1.f - lyB) * lxB;
        float b10 = lyB * (1.f - lxB),         b11 = lyB * lxB;
        if (!(vyB && XB > -1.f && XB < 40.f)) { b00 = b01 = b10 = b11 = 0.f; }

        U4 cA00, cA01, cA10, cA11, cB00, cB01, cB10, cB11;
        cA00.u = imgA[(y0A  * 40 + x0A ) * 32 + lane];
        cA01.u = imgA[(y0A  * 40 + x1iA) * 32 + lane];
        cA10.u = imgA[(y1iA * 40 + x0A ) * 32 + lane];
        cA11.u = imgA[(y1iA * 40 + x1iA) * 32 + lane];
        cB00.u = imgB[(y0B  * 40 + x0B ) * 32 + lane];
        cB01.u = imgB[(y0B  * 40 + x1iB) * 32 + lane];
        cB10.u = imgB[(y1iB * 40 + x0B ) * 32 + lane];
        cB11.u = imgB[(y1iB * 40 + x1iB) * 32 + lane];

        U4 oA, oB;
        #pragma unroll
        for (int j = 0; j < 4; ++j) {
            float2 f0 = __half22float2(cA00.h[j]);
            float2 f1 = __half22float2(cA01.h[j]);
            float2 f2 = __half22float2(cA10.h[j]);
            float2 f3 = __half22float2(cA11.h[j]);
            oA.h[j] = __floats2half2_rn(
                f0.x * a00 + f1.x * a01 + f2.x * a10 + f3.x * a11,
                f0.y * a00 + f1.y * a01 + f2.y * a10 + f3.y * a11);
            f0 = __half22float2(cB00.h[j]);
            f1 = __half22float2(cB01.h[j]);
            f2 = __half22float2(cB10.h[j]);
            f3 = __half22float2(cB11.h[j]);
            oB.h[j] = __floats2half2_rn(
                f0.x * b00 + f1.x * b01 + f2.x * b10 + f3.x * b11,
                f0.y * b00 + f1.y * b01 + f2.y * b10 + f3.y * b11);
        }
        *(uint4*)wrA = oA.u;
        *(uint4*)wrB = oB.u;
        __syncwarp();

        const int hw = h * 7 + w;
        {
            uint4 wv;
            wv.x = s[wp * 132 + pA0];
            wv.y = s[(wp + 8) * 132 + pA0];
            wv.z = s[wp * 132 + pA4];
            wv.w = s[(wp + 8) * 132 + pA4];
            *(uint4*)(outb + (size_t)(hw * 8 + cc0) * TILE_BYTES
                      + (ks0 * 32 + wp * 4 + tg0) * 16) = wv;
            wv.x = s[wp * 132 + pB0];
            wv.y = s[(wp + 8) * 132 + pB0];
            wv.z = s[wp * 132 + pB4];
            wv.w = s[(wp + 8) * 132 + pB4];
            *(uint4*)(outb + (size_t)(hw * 8 + cc1) * TILE_BYTES
                      + (ks1 * 32 + wp * 4 + tg1) * 16) = wv;
        }
        __syncwarp();
    }
}

// ---------------- cp.async helpers ----------------
#define STAGE_BYTES 16384
#define NSTAGE 4
#define SM_TOTAL (NSTAGE * STAGE_BYTES)   // 64 KB

__device__ __forceinline__ void cp16(void* smem_dst, const void* gmem_src) {
    unsigned s = (unsigned)__cvta_generic_to_shared(smem_dst);
    asm volatile("cp.async.cg.shared.global [%0], [%1], 16;" :: "r"(s), "l"(gmem_src));
}
__device__ __forceinline__ void cp_commit() { asm volatile("cp.async.commit_group;"); }
template<int N> __device__ __forceinline__ void cp_wait() {
    asm volatile("cp.async.wait_group %0;" :: "n"(N));
}

// ===== GEMM1 split-K: 128x128x32 CTA, 128 threads, 4 warps 64x64, 2 CTAs/SM =====
__global__ void __launch_bounds__(128, 2)
gemm1_splitk()
{
    extern __shared__ char sm[];
    const int tid = threadIdx.x, lane = tid & 31, wid = tid >> 5;
    const int warp_m = wid >> 1, warp_n = wid & 1;
    const int ntile = blockIdx.x, mtile = blockIdx.y, kz = blockIdx.z;

    const char* Ag = (const char*)g_roiT + (size_t)(mtile * NCHUNK + kz * HCHUNK) * TILE_BYTES;
    const char* Bg = (const char*)g_w1tT + (size_t)(ntile * NCHUNK + kz * HCHUNK) * TILE_BYTES;

    float acc[4][8][4];
    #pragma unroll
    for (int mt = 0; mt < 4; ++mt)
        #pragma unroll
        for (int nt = 0; nt < 8; ++nt)
            #pragma unroll
            for (int j = 0; j < 4; ++j) acc[mt][nt][j] = 0.f;

    #pragma unroll
    for (int t = 0; t < 3; ++t) {
        char* sa = sm + t * STAGE_BYTES;
        #pragma unroll
        for (int i = 0; i < 4; ++i) {
            const int off = (tid + i * 128) * 16;
            cp16(sa + off,        Ag + (size_t)t * TILE_BYTES + off);
            cp16(sa + 8192 + off, Bg + (size_t)t * TILE_BYTES + off);
        }
        cp_commit();
    }

    const int aBase = warp_m * 4096 + lane * 16;
    const int bBase = 8192 + warp_n * 4096 + lane * 16;

    for (int t = 0; t < HCHUNK; ++t) {
        cp_wait<2>();
        __syncthreads();

        if (t + 3 < HCHUNK) {
            char* sa = sm + ((t + 3) & 3) * STAGE_BYTES;
            #pragma unroll
            for (int i = 0; i < 4; ++i) {
                const int off = (tid + i * 128) * 16;
                cp16(sa + off,        Ag + (size_t)(t + 3) * TILE_BYTES + off);
                cp16(sa + 8192 + off, Bg + (size_t)(t + 3) * TILE_BYTES + off);
            }
        }
        cp_commit();

        const char* S = sm + (t & 3) * STAGE_BYTES;
        #pragma unroll
        for (int ks = 0; ks < 2; ++ks) {
            uint4 af[4];
            #pragma unroll
            for (int mt = 0; mt < 4; ++mt)
                af[mt] = *(const uint4*)(S + aBase + mt * 1024 + ks * 512);
            uint4 bq[4];
            #pragma unroll
            for (int np = 0; np < 4; ++np)
                bq[np] = *(const uint4*)(S + bBase + np * 1024 + ks * 512);
            #pragma unroll
            for (int np = 0; np < 4; ++np) {
                #pragma unroll
                for (int mt = 0; mt < 4; ++mt) {
                    asm volatile(
                        "mma.sync.aligned.m16n8k16.row.col.f32.f16.f16.f32 "
                        "{%0,%1,%2,%3}, {%4,%5,%6,%7}, {%8,%9}, {%0,%1,%2,%3};"
                        : "+f"(acc[mt][np * 2][0]), "+f"(acc[mt][np * 2][1]),
                          "+f"(acc[mt][np * 2][2]), "+f"(acc[mt][np * 2][3])
                        : "r"(af[mt].x), "r"(af[mt].y), "r"(af[mt].z), "r"(af[mt].w),
                          "r"(bq[np].x), "r"(bq[np].y));
                    asm volatile(
                        "mma.sync.aligned.m16n8k16.row.col.f32.f16.f16.f32 "
                        "{%0,%1,%2,%3}, {%4,%5,%6,%7}, {%8,%9}, {%0,%1,%2,%3};"
                        : "+f"(acc[mt][np * 2 + 1][0]), "+f"(acc[mt][np * 2 + 1][1]),
                          "+f"(acc[mt][np * 2 + 1][2]), "+f"(acc[mt][np * 2 + 1][3])
                        : "r"(af[mt].x), "r"(af[mt].y), "r"(af[mt].z), "r"(af[mt].w),
                          "r"(bq[np].z), "r"(bq[np].w));
                }
            }
        }
    }

    // write fp32 partials row-major
    const int g = lane >> 2, tg = lane & 3;
    float* part = g_part + (size_t)kz * RTOT * HID;
    #pragma unroll
    for (int nt = 0; nt < 8; ++nt) {
        const int col = ntile * 128 + warp_n * 64 + nt * 8 + tg * 2;
        #pragma unroll
        for (int mt = 0; mt < 4; ++mt) {
            const int row = mtile * 128 + warp_m * 64 + mt * 16 + g;
            float2 v;
            v.x = acc[mt][nt][0]; v.y = acc[mt][nt][1];
            *(float2*)&part[(size_t)row * HID + col] = v;
            v.x = acc[mt][nt][2]; v.y = acc[mt][nt][3];
            *(float2*)&part[(size_t)(row + 8) * HID + col] = v;
        }
    }
}

// ===== combine partials + bias + BN + ReLU -> h1T fragment tiles =====
__global__ void __launch_bounds__(256)
combine1(const float* __restrict__ bias, const float* __restrict__ gamma,
         const float* __restrict__ beta, const float* __restrict__ mean,
         const float* __restrict__ var)
{
    __shared__ __half2 st2[128 * 66];
    const int ntile = blockIdx.x, mtile = blockIdx.y;
    const int tid = threadIdx.x;

    #pragma unroll
    for (int it = 0; it < 16; ++it) {
        const int u = tid + it * 256;           // 0..4095 (float4 units)
        const int row = u >> 5;
        const int c4 = (u & 31) * 4;
        const size_t gp = (size_t)(mtile * 128 + row) * HID + ntile * 128 + c4;
        const float4 a = *(const float4*)&g_part[gp];
        const float4 b = *(const float4*)&g_part[(size_t)RTOT * HID + gp];
        const int cg = ntile * 128 + c4;
        float o[4];
        const float sum[4] = {a.x + b.x, a.y + b.y, a.z + b.z, a.w + b.w};
        #pragma unroll
        for (int j = 0; j < 4; ++j) {
            const float sc = gamma[cg + j] * rsqrtf(var[cg + j] + EPS);
            const float sh = (bias[cg + j] - mean[cg + j]) * sc + beta[cg + j];
            o[j] = fmaxf(sum[j] * sc + sh, 0.f);
        }
        st2[row * 66 + (c4 >> 1)]     = __floats2half2_rn(o[0], o[1]);
        st2[row * 66 + (c4 >> 1) + 1] = __floats2half2_rn(o[2], o[3]);
    }
    __syncthreads();

    char* dst = (char*)g_h1T + (size_t)(mtile * 16 + ntile * 4) * TILE_BYTES;
    #pragma unroll
    for (int it = 0; it < 8; ++it) {
        const int u = tid + it * 256;            // 0..2047 (16B slots)
        const int chunkl = u >> 9, sidx = u & 511;
        const int subr = sidx >> 6, rem = sidx & 63;
        const int ks2 = rem >> 5, ln = rem & 31;
        const int g2 = ln >> 2, tg2 = ln & 3;
        const int row = subr * 16 + g2;
        const int kp = chunkl * 16 + ks2 * 8 + tg2;
        uint4 wv;
        wv.x = *(const uint32_t*)&st2[row * 66 + kp];
        wv.y = *(const uint32_t*)&st2[(row + 8) * 66 + kp];
        wv.z = *(const uint32_t*)&st2[row * 66 + kp + 4];
        wv.w = *(const uint32_t*)&st2[(row + 8) * 66 + kp + 4];
        *(uint4*)(dst + (size_t)chunkl * TILE_BYTES + subr * 1024 + rem * 16) = wv;
    }
}

// ===== GEMM2: 128x128x32 CTA, 8 warps ks-split, 4-stage (proven 272 build) =====
__global__ void __launch_bounds__(256, 1)
gemm_tc(const char* __restrict__ Afrag, const char* __restrict__ Bfrag, int nchunk,
        float* __restrict__ outMax,
        const float* __restrict__ bias, const float* __restrict__ gamma,
        const float* __restrict__ beta, const float* __restrict__ mean,
        const float* __restrict__ var)
{
    extern __shared__ char sm[];
    const int tid = threadIdx.x, lane = tid & 31, wid = tid >> 5;
    const int ksw = wid >> 2;
    const int wq  = wid & 3;
    const int warp_m = wq >> 1, warp_n = wq & 1;
    const int ntile = blockIdx.x, mtile = blockIdx.y;

    const char* Ag = Afrag + (size_t)mtile * nchunk * TILE_BYTES;
    const char* Bg = Bfrag + (size_t)ntile * nchunk * TILE_BYTES;

    float acc[4][8][4];
    #pragma unroll
    for (int mt = 0; mt < 4; ++mt)
        #pragma unroll
        for (int nt = 0; nt < 8; ++nt)
            #pragma unroll
            for (int j = 0; j < 4; ++j) acc[mt][nt][j] = 0.f;

    #pragma unroll
    for (int t = 0; t < 3; ++t) {
        char* sa = sm + t * STAGE_BYTES;
        #pragma unroll
        for (int i = 0; i < 2; ++i) {
            const int off = (tid + i * 256) * 16;
            cp16(sa + off,        Ag + (size_t)t * TILE_BYTES + off);
            cp16(sa + 8192 + off, Bg + (size_t)t * TILE_BYTES + off);
        }
        cp_commit();
    }

    const int aBase = warp_m * 4096 + ksw * 512 + lane * 16;
    const int bBase = 8192 + warp_n * 4096 + ksw * 512 + lane * 16;

    for (int t = 0; t < nchunk; ++t) {
        cp_wait<2>();
        __syncthreads();

        if (t + 3 < nchunk) {
            char* sa = sm + ((t + 3) & 3) * STAGE_BYTES;
            #pragma unroll
            for (int i = 0; i < 2; ++i) {
                const int off = (tid + i * 256) * 16;
                cp16(sa + off,        Ag + (size_t)(t + 3) * TILE_BYTES + off);
                cp16(sa + 8192 + off, Bg + (size_t)(t + 3) * TILE_BYTES + off);
            }
        }
        cp_commit();

        const char* S = sm + (t & 3) * STAGE_BYTES;
        uint4 af[4];
        #pragma unroll
        for (int mt = 0; mt < 4; ++mt)
            af[mt] = *(const uint4*)(S + aBase + mt * 1024);
        uint4 bq[4];
        #pragma unroll
        for (int np = 0; np < 4; ++np)
            bq[np] = *(const uint4*)(S + bBase + np * 1024);
        #pragma unroll
        for (int np = 0; np < 4; ++np) {
            #pragma unroll
            for (int mt = 0; mt < 4; ++mt) {
                asm volatile(
                    "mma.sync.aligned.m16n8k16.row.col.f32.f16.f16.f32 "
                    "{%0,%1,%2,%3}, {%4,%5,%6,%7}, {%8,%9}, {%0,%1,%2,%3};"
                    : "+f"(acc[mt][np * 2][0]), "+f"(acc[mt][np * 2][1]),
                      "+f"(acc[mt][np * 2][2]), "+f"(acc[mt][np * 2][3])
                    : "r"(af[mt].x), "r"(af[mt].y), "r"(af[mt].z), "r"(af[mt].w),
                      "r"(bq[np].x), "r"(bq[np].y));
                asm volatile(
                    "mma.sync.aligned.m16n8k16.row.col.f32.f16.f16.f32 "
                    "{%0,%1,%2,%3}, {%4,%5,%6,%7}, {%8,%9}, {%0,%1,%2,%3};"
                    : "+f"(acc[mt][np * 2 + 1][0]), "+f"(acc[mt][np * 2 + 1][1]),
                      "+f"(acc[mt][np * 2 + 1][2]), "+f"(acc[mt][np * 2 + 1][3])
                    : "r"(af[mt].x), "r"(af[mt].y), "r"(af[mt].z), "r"(af[mt].w),
                      "r"(bq[np].z), "r"(bq[np].w));
            }
        }
    }

    const int g = lane >> 2, tg = lane & 3;

    // ---- ks-split combine ----
    __syncthreads();
    {
        float2* red2 = (float2*)sm;
        if (ksw == 1) {
            #pragma unroll
            for (int nt = 0; nt < 8; ++nt) {
                const int col2 = warp_n * 32 + nt * 4 + tg;
                #pragma unroll
                for (int mt = 0; mt < 4; ++mt) {
                    const int row = warp_m * 64 + mt * 16 + g;
                    const int ph = col2 ^ (g << 2);
                    float2 v0; v0.x = acc[mt][nt][0]; v0.y = acc[mt][nt][1];
                    float2 v1; v1.x = acc[mt][nt][2]; v1.y = acc[mt][nt][3];
                    red2[row * 64 + ph] = v0;
                    red2[(row + 8) * 64 + ph] = v1;
                }
            }
        }
        __syncthreads();
        if (ksw == 0) {
            #pragma unroll
            for (int nt = 0; nt < 8; ++nt) {
                const int col2 = warp_n * 32 + nt * 4 + tg;
                #pragma unroll
                for (int mt = 0; mt < 4; ++mt) {
                    const int row = warp_m * 64 + mt * 16 + g;
                    const int ph = col2 ^ (g << 2);
                    const float2 v0 = red2[row * 64 + ph];
                    const float2 v1 = red2[(row + 8) * 64 + ph];
                    acc[mt][nt][0] += v0.x; acc[mt][nt][1] += v0.y;
                    acc[mt][nt][2] += v1.x; acc[mt][nt][3] += v1.y;
                }
            }
        }
    }

    if (ksw == 0) {
        // fused BN + ReLU + max over 8-row groups -> outMax[node][col]
        const int n0 = ntile * 128 + warp_n * 64;
        #pragma unroll
        for (int nt = 0; nt < 8; ++nt) {
            const int c0 = n0 + nt * 8 + tg * 2;
            const float s0 = gamma[c0]     * rsqrtf(var[c0]     + EPS);
            const float s1 = gamma[c0 + 1] * rsqrtf(var[c0 + 1] + EPS);
            const float h0  = (bias[c0]     - mean[c0])     * s0 + beta[c0];
            const float h1v = (bias[c0 + 1] - mean[c0 + 1]) * s1 + beta[c0 + 1];
            #pragma unroll
            for (int mt = 0; mt < 4; ++mt) {
                float v0 = fmaxf(acc[mt][nt][0] * s0 + h0,  0.f);
                float v1 = fmaxf(acc[mt][nt][1] * s1 + h1v, 0.f);
                float v2 = fmaxf(acc[mt][nt][2] * s0 + h0,  0.f);
                float v3 = fmaxf(acc[mt][nt][3] * s1 + h1v, 0.f);
                #pragma unroll
                for (int d = 4; d <= 16; d <<= 1) {
                    v0 = fmaxf(v0, __shfl_xor_sync(0xffffffffu, v0, d));
                    v1 = fmaxf(v1, __shfl_xor_sync(0xffffffffu, v1, d));
                    v2 = fmaxf(v2, __shfl_xor_sync(0xffffffffu, v2, d));
                    v3 = fmaxf(v3, __shfl_xor_sync(0xffffffffu, v3, d));
                }
                if (lane < 4) {
                    const int node0 = mtile * 16 + warp_m * 8 + mt * 2;
                    float2 a; a.x = v0; a.y = v1;
                    float2 b; b.x = v2; b.y = v3;
                    *(float2*)&outMax[(size_t)node0 * DD + c0] = a;
                    *(float2*)&outMax[(size_t)(node0 + 1) * DD + c0] = b;
                }
            }
        }
    }
}

// ---------------- launch ----------------
extern "C" void kernel_launch(void* const* d_in, const int* in_sizes, int n_in,
                              void* d_out, int out_size)
{
    const float* images = (const float*)d_in[0];
    const int*   kf     = (const int*)  d_in[1];
    const float* boxes  = (const float*)d_in[2];
    const float* w1     = (const float*)d_in[3];
    const float* b1     = (const float*)d_in[4];
    const float* g1     = (const float*)d_in[5];
    const float* bt1    = (const float*)d_in[6];
    const float* m1     = (const float*)d_in[7];
    const float* v1     = (const float*)d_in[8];
    const float* w2     = (const float*)d_in[9];
    const float* b2     = (const float*)d_in[10];
    const float* g2     = (const float*)d_in[11];
    const float* bt2    = (const float*)d_in[12];
    const float* m2     = (const float*)d_in[13];
    const float* v2     = (const float*)d_in[14];
    float* out = (float*)d_out;

    char *h1T, *w2T;
    cudaGetSymbolAddress((void**)&h1T, g_h1T);
    cudaGetSymbolAddress((void**)&w2T, g_w2T);

    cudaFuncSetAttribute(gemm1_splitk, cudaFuncAttributeMaxDynamicSharedMemorySize, SM_TOTAL);
    cudaFuncSetAttribute(gemm_tc, cudaFuncAttributeMaxDynamicSharedMemorySize, SM_TOTAL);

    // order chosen so gemm1_splitk is launch #4 (ncu capture slot)
    transpose_img<<<dim3(NPIX / 32, CCH / 64, NF), dim3(32, 8)>>>(images);
    transpose_w1<<<HID, 128>>>(w1);
    roi_gather_frag<<<dim3(256, 7), 256>>>(kf, boxes);
    gemm1_splitk<<<dim3(4, 32, 2), 128, SM_TOTAL>>>();
    combine1<<<dim3(4, 32), 256>>>(b1, g1, bt1, m1, v1);
    repack_w2<<<DD, 128>>>(w2);
    gemm_tc<<<dim3(4, 32), 256, SM_TOTAL>>>(
        h1T, w2T, 16, out, b2, g2, bt2, m2, v2);
}